// round 5
// baseline (speedup 1.0000x reference)
#include <cuda_runtime.h>
#include <cuda_bf16.h>
#include <math.h>

#define B 128
#define T 32
#define S 512
#define H 1024
#define IN_DIM 1024
#define G4 4096          // 4*H
#define KREC 2048        // 2*H
#define K3 3072          // folded gates K

#define SK_GATES 8
#define SK_HTIL 16
#define NSPLIT 8

// ---- output offsets (flattened tuple, fp32) ----
#define OFF_OUT   0ull
#define OFF_H     4194304ull
#define OFF_C     4325376ull
#define OFF_HA    4456448ull
#define OFF_ATTN  4587520ull
#define OFF_PATTN 6684672ull
#define OFF_P     6750208ull
#define OFF_DEHY  6754304ull
#define OFF_LOSS  6885376ull

// ---- scratch ----
__device__ float g_Xg[(size_t)B * T * G4];
__device__ float g_biasg[G4];
__device__ float g_bfold[G4];                       // Wr_a @ b_out
__device__ float g_gates_part[SK_GATES * B * G4];
__device__ float g_htil_part[SK_HTIL * B * H];
__device__ float g_h[B * H];
__device__ float g_c[B * H];
__device__ float g_logits[B * S];
__device__ float g_part_acc[B * NSPLIT * H];
__device__ float g_part_m[B * NSPLIT];
__device__ float g_part_l[B * NSPLIT];
__device__ float g_Wfold32[(size_t)G4 * KREC];      // Wr_a @ W_out (fp32 staging)

// bf16 hi/lo weights
__device__ __nv_bfloat16 g_Wr_h[(size_t)G4 * KREC];   // [W_ih[:,IN:], W_hh]
__device__ __nv_bfloat16 g_Wr_l[(size_t)G4 * KREC];
__device__ __nv_bfloat16 g_Wbig_h[(size_t)G4 * K3];   // [Wfold | Wr_h]
__device__ __nv_bfloat16 g_Wbig_l[(size_t)G4 * K3];
__device__ __nv_bfloat16 g_Wat_h[H * H];
__device__ __nv_bfloat16 g_Wat_l[H * H];
__device__ __nv_bfloat16 g_Wout_h[H * KREC];
__device__ __nv_bfloat16 g_Wout_l[H * KREC];
__device__ __nv_bfloat16 g_WoutT_h[KREC * H];
__device__ __nv_bfloat16 g_WoutT_l[KREC * H];
__device__ __nv_bfloat16 g_Wih_h[(size_t)G4 * IN_DIM];
__device__ __nv_bfloat16 g_Wih_l[(size_t)G4 * IN_DIM];
__device__ __nv_bfloat16 g_in_h[(size_t)B * T * IN_DIM];
__device__ __nv_bfloat16 g_in_l[(size_t)B * T * IN_DIM];
// bf16 hi/lo activations
__device__ __nv_bfloat16 g_Arec_h[B * KREC];          // [ha0, h0] for step 0
__device__ __nv_bfloat16 g_Arec_l[B * KREC];
__device__ __nv_bfloat16 g_A3_h[B * K3];              // [c_enc, h, h]
__device__ __nv_bfloat16 g_A3_l[B * K3];
__device__ __nv_bfloat16 g_hist_h[(size_t)B * T * KREC]; // [c_enc_t, h_t], row = b*T+t
__device__ __nv_bfloat16 g_hist_l[(size_t)B * T * KREC];
__device__ __nv_bfloat16 g_h_h[B * H];
__device__ __nv_bfloat16 g_h_l[B * H];

__device__ __forceinline__ void split2(float x, __nv_bfloat16& hi, __nv_bfloat16& lo)
{
    hi = __float2bfloat16(x);
    lo = __float2bfloat16(x - __bfloat162float(hi));
}
__device__ __forceinline__ float join2(__nv_bfloat16 hi, __nv_bfloat16 lo)
{
    return __bfloat162float(hi) + __bfloat162float(lo);
}

// ============================================================
// Tensor-core GEMM: C = A @ W.T with bf16x3 split.
// ============================================================
#define SKP  40
#define TILE (128 * SKP)
#define SMEM_BYTES (2 * 4 * TILE * 2)

__device__ __forceinline__ void ldsm4(unsigned* r, unsigned addr)
{
    asm volatile("ldmatrix.sync.aligned.m8n8.x4.shared.b16 {%0,%1,%2,%3}, [%4];"
                 : "=r"(r[0]), "=r"(r[1]), "=r"(r[2]), "=r"(r[3]) : "r"(addr));
}
__device__ __forceinline__ void mma16816(float* d, const unsigned* a, const unsigned* b)
{
    asm volatile("mma.sync.aligned.m16n8k16.row.col.f32.bf16.bf16.f32 "
                 "{%0,%1,%2,%3}, {%4,%5,%6,%7}, {%8,%9}, {%0,%1,%2,%3};"
                 : "+f"(d[0]), "+f"(d[1]), "+f"(d[2]), "+f"(d[3])
                 : "r"(a[0]), "r"(a[1]), "r"(a[2]), "r"(a[3]), "r"(b[0]), "r"(b[1]));
}
#define CP16(dst, src) \
    asm volatile("cp.async.cg.shared.global [%0], [%1], 16;" :: "r"(dst), "l"(src))
#define CP_COMMIT() asm volatile("cp.async.commit_group;")
#define CP_WAIT(n)  asm volatile("cp.async.wait_group %0;" :: "n"(n))

__global__ __launch_bounds__(256)
void hgemm_tn(const __nv_bfloat16* __restrict__ Ah, const __nv_bfloat16* __restrict__ Al,
              int lda,
              const __nv_bfloat16* __restrict__ Wh, const __nv_bfloat16* __restrict__ Wl,
              int ldw,
              float* __restrict__ Cpart, int M, int N, int Kslice,
              const float* __restrict__ bias)
{
    extern __shared__ __nv_bfloat16 smem[];
    const int bn = blockIdx.x, bm = blockIdx.y, bz = blockIdx.z;
    Ah += (size_t)bm * 128 * lda + (size_t)bz * Kslice;
    Al += (size_t)bm * 128 * lda + (size_t)bz * Kslice;
    Wh += (size_t)bn * 128 * ldw + (size_t)bz * Kslice;
    Wl += (size_t)bn * 128 * ldw + (size_t)bz * Kslice;
    float* C = Cpart + (size_t)bz * M * N + (size_t)bm * 128 * N + (size_t)bn * 128;

    const int tid = threadIdx.x;
    const int warp = tid >> 5, lane = tid & 31;
    const int wm = (warp >> 2) * 64;
    const int wn = (warp & 3) * 32;

    const unsigned sbase = (unsigned)__cvta_generic_to_shared(smem);

    float acc[4][4][4];
#pragma unroll
    for (int i = 0; i < 4; i++)
#pragma unroll
        for (int j = 0; j < 4; j++)
#pragma unroll
            for (int q = 0; q < 4; q++) acc[i][j][q] = 0.f;

    const int nIter = Kslice >> 5;

    auto load_stage = [&](int stage, int ko) {
        unsigned sb = sbase + (unsigned)(stage * 4 * TILE) * 2;
#pragma unroll
        for (int i = 0; i < 2; i++) {
            int idx = i * 256 + tid;
            int row = idx >> 2, ch = (idx & 3) * 8;
            unsigned doff = (unsigned)(row * SKP + ch) * 2;
            size_t ga = (size_t)row * lda + ko + ch;
            size_t gw = (size_t)row * ldw + ko + ch;
            CP16(sb + doff,                         Ah + ga);
            CP16(sb + (unsigned)TILE * 2 + doff,    Al + ga);
            CP16(sb + (unsigned)TILE * 4 + doff,    Wh + gw);
            CP16(sb + (unsigned)TILE * 6 + doff,    Wl + gw);
        }
    };

    load_stage(0, 0);
    CP_COMMIT();
    if (nIter > 1) { load_stage(1, 32); CP_COMMIT(); }

    const int rA = lane & 15;
    const int kA = (lane >> 4) * 8;
    const int rB = (lane & 7) + ((lane & 16) ? 8 : 0);
    const int kB = (lane & 8);

    for (int it = 0; it < nIter; it++) {
        if (it + 1 < nIter) { CP_WAIT(1); } else { CP_WAIT(0); }
        __syncthreads();

        unsigned base = sbase + (unsigned)((it & 1) * 4 * TILE) * 2;
#pragma unroll
        for (int k16 = 0; k16 < 32; k16 += 16) {
            unsigned ah[4][4], al[4][4], bh[4][2], bl[4][2];
#pragma unroll
            for (int mt = 0; mt < 4; mt++) {
                unsigned ad = base + (unsigned)((wm + mt * 16 + rA) * SKP + k16 + kA) * 2;
                ldsm4(ah[mt], ad);
                ldsm4(al[mt], ad + (unsigned)TILE * 2);
            }
#pragma unroll
            for (int np = 0; np < 2; np++) {
                unsigned bd = base + (unsigned)TILE * 4 +
                              (unsigned)((wn + np * 16 + rB) * SKP + k16 + kB) * 2;
                unsigned r[4];
                ldsm4(r, bd);
                bh[np * 2][0] = r[0]; bh[np * 2][1] = r[1];
                bh[np * 2 + 1][0] = r[2]; bh[np * 2 + 1][1] = r[3];
                ldsm4(r, bd + (unsigned)TILE * 2);
                bl[np * 2][0] = r[0]; bl[np * 2][1] = r[1];
                bl[np * 2 + 1][0] = r[2]; bl[np * 2 + 1][1] = r[3];
            }
#pragma unroll
            for (int mt = 0; mt < 4; mt++)
#pragma unroll
                for (int nt = 0; nt < 4; nt++) {
                    mma16816(acc[mt][nt], ah[mt], bh[nt]);
                    mma16816(acc[mt][nt], al[mt], bh[nt]);
                    mma16816(acc[mt][nt], ah[mt], bl[nt]);
                }
        }
        __syncthreads();
        if (it + 2 < nIter) { load_stage(it & 1, (it + 2) * 32); CP_COMMIT(); }
    }

    const int er = lane >> 2;
    const int ec = (lane & 3) * 2;
#pragma unroll
    for (int mt = 0; mt < 4; mt++)
#pragma unroll
        for (int nt = 0; nt < 4; nt++) {
            int r0 = wm + mt * 16 + er;
            int c0 = wn + nt * 8 + ec;
            float b0 = 0.f, b1 = 0.f;
            if (bias != nullptr) {
                b0 = bias[bn * 128 + c0];
                b1 = bias[bn * 128 + c0 + 1];
            }
            float* p0 = C + (size_t)r0 * N + c0;
            float* p1 = C + (size_t)(r0 + 8) * N + c0;
            p0[0] = acc[mt][nt][0] + b0;
            p0[1] = acc[mt][nt][1] + b1;
            p1[0] = acc[mt][nt][2] + b0;
            p1[1] = acc[mt][nt][3] + b1;
        }
}

// ============================================================
// Setup kernels
// ============================================================
__global__ void prep_kernel(const float* __restrict__ W_ih, const float* __restrict__ W_hh,
                            const float* __restrict__ b_ih, const float* __restrict__ b_hh,
                            const float* __restrict__ W_attn, const float* __restrict__ W_out,
                            const float* __restrict__ b_out, const float* __restrict__ input_)
{
    size_t stride = (size_t)gridDim.x * blockDim.x;
    size_t start = (size_t)blockIdx.x * blockDim.x + threadIdx.x;
    for (size_t idx = start; idx < (size_t)G4 * KREC; idx += stride) {
        int n = (int)(idx >> 11);
        int k = (int)(idx & 2047);
        float v = (k < H) ? W_ih[(size_t)n * KREC + IN_DIM + k]
                          : W_hh[(size_t)n * H + (k - H)];
        split2(v, g_Wr_h[idx], g_Wr_l[idx]);
    }
    for (size_t idx = start; idx < (size_t)H * H; idx += stride) {
        int n = (int)(idx >> 10), k = (int)(idx & 1023);
        split2(W_attn[(size_t)k * H + n], g_Wat_h[idx], g_Wat_l[idx]);
    }
    for (size_t idx = start; idx < (size_t)H * KREC; idx += stride)
        split2(W_out[idx], g_Wout_h[idx], g_Wout_l[idx]);
    // W_out transposed [2H, H]
    for (size_t idx = start; idx < (size_t)KREC * H; idx += stride) {
        int k2 = (int)(idx >> 10), j = (int)(idx & 1023);
        split2(W_out[(size_t)j * KREC + k2], g_WoutT_h[idx], g_WoutT_l[idx]);
    }
    for (size_t idx = start; idx < (size_t)G4 * IN_DIM; idx += stride) {
        int n = (int)(idx >> 10), k = (int)(idx & 1023);
        split2(W_ih[(size_t)n * KREC + k], g_Wih_h[idx], g_Wih_l[idx]);
    }
    for (size_t idx = start; idx < (size_t)B * T * IN_DIM; idx += stride)
        split2(input_[idx], g_in_h[idx], g_in_l[idx]);
    for (size_t idx = start; idx < (size_t)G4; idx += stride) {
        g_biasg[idx] = b_ih[idx] + b_hh[idx];
        // bfold[n] = sum_j Wr_a[n,j] * b_out[j]  (fp32)
        const float* wa = W_ih + idx * KREC + IN_DIM;
        float s = 0.f;
        for (int j = 0; j < H; j++) s += wa[j] * b_out[j];
        g_bfold[idx] = s;
    }
}

// pack Wbig = [split(Wfold32) | Wr cols H..2H)]
__global__ void pack_wbig(void)
{
    size_t stride = (size_t)gridDim.x * blockDim.x;
    for (size_t idx = (size_t)blockIdx.x * blockDim.x + threadIdx.x;
         idx < (size_t)G4 * K3; idx += stride) {
        int n = (int)(idx / K3);
        int k = (int)(idx % K3);
        if (k < KREC) {
            split2(g_Wfold32[(size_t)n * KREC + k], g_Wbig_h[idx], g_Wbig_l[idx]);
        } else {
            size_t src = (size_t)n * KREC + H + (k - KREC);
            g_Wbig_h[idx] = g_Wr_h[src];
            g_Wbig_l[idx] = g_Wr_l[src];
        }
    }
}

__global__ void init_kernel(const float* __restrict__ hh, const float* __restrict__ hc,
                            const float* __restrict__ ha)
{
    int idx = blockIdx.x * blockDim.x + threadIdx.x;
    if (idx < B * H) {
        int b = idx >> 10, n = idx & 1023;
        g_h[idx] = hh[idx];
        g_c[idx] = hc[idx];
        split2(ha[idx], g_Arec_h[b * KREC + n], g_Arec_l[b * KREC + n]);
        split2(hh[idx], g_Arec_h[b * KREC + H + n], g_Arec_l[b * KREC + H + n]);
    }
}

// ============================================================
// LSTM cell: reduce gate partials + Xg (+bfold for t>=1), update h/c
// ============================================================
__global__ void lstm_step(int t)
{
    int idx = blockIdx.x * blockDim.x + threadIdx.x;   // B*H
    int b = idx >> 10, n = idx & 1023;
    size_t row = ((size_t)b * T + t) * G4;
    float gi = g_Xg[row + n];
    float gf = g_Xg[row + H + n];
    float gg = g_Xg[row + 2 * H + n];
    float go = g_Xg[row + 3 * H + n];
    if (t > 0) {
        gi += g_bfold[n];
        gf += g_bfold[H + n];
        gg += g_bfold[2 * H + n];
        go += g_bfold[3 * H + n];
    }
#pragma unroll
    for (int p = 0; p < SK_GATES; p++) {
        const float* gp = g_gates_part + (size_t)p * B * G4 + (size_t)b * G4;
        gi += gp[n]; gf += gp[H + n]; gg += gp[2 * H + n]; go += gp[3 * H + n];
    }
    float i_ = 1.f / (1.f + expf(-gi));
    float f_ = 1.f / (1.f + expf(-gf));
    float g_ = tanhf(gg);
    float o_ = 1.f / (1.f + expf(-go));
    float c_new = f_ * g_c[idx] + i_ * g_;
    float h_new = o_ * tanhf(c_new);
    g_c[idx] = c_new;
    g_h[idx] = h_new;
    __nv_bfloat16 hH, hL;
    split2(h_new, hH, hL);
    g_h_h[idx] = hH; g_h_l[idx] = hL;
    g_A3_h[b * K3 + H + n] = hH;      g_A3_l[b * K3 + H + n] = hL;
    g_A3_h[b * K3 + 2 * H + n] = hH;  g_A3_l[b * K3 + 2 * H + n] = hL;
    size_t hrow = ((size_t)b * T + t) * KREC;
    g_hist_h[hrow + H + n] = hH;      g_hist_l[hrow + H + n] = hL;
}

// ============================================================
// One-pass flash attention over a split of S (float4 loads).
// grid (B, NSPLIT=8), 256 threads, 8 s-rows per warp.
// ============================================================
__global__ __launch_bounds__(256)
void flash_step(const float* __restrict__ enc)
{
    int b = blockIdx.x, sp = blockIdx.y;
    __shared__ float htil[H];
    __shared__ float accS[8][1024];
    __shared__ float wm[8], wl[8], wf[8];
    int tid = threadIdx.x;

    for (int j = tid; j < H; j += 256) {
        float s = 0.f;
#pragma unroll
        for (int p = 0; p < SK_HTIL; p++) s += g_htil_part[(size_t)p * B * H + b * H + j];
        htil[j] = s;
    }
    __syncthreads();

    int warp = tid >> 5, lane = tid & 31;
    float m = -1e30f, l = 0.f;
    float4 acc[8];
#pragma unroll
    for (int i = 0; i < 8; i++) acc[i] = make_float4(0.f, 0.f, 0.f, 0.f);

    float4 ht[8];
#pragma unroll
    for (int i = 0; i < 8; i++) ht[i] = *(const float4*)&htil[i * 128 + lane * 4];

    const float* encb = enc + (size_t)b * S * H;
    int s0 = sp * (S / NSPLIT) + warp * 8;
    for (int si = 0; si < 8; si++) {
        int s = s0 + si;
        const float4* er = (const float4*)(encb + (size_t)s * H) + lane;
        float4 v[8];
#pragma unroll
        for (int i = 0; i < 8; i++) v[i] = er[i * 32];
        float d = 0.f;
#pragma unroll
        for (int i = 0; i < 8; i++)
            d += v[i].x * ht[i].x + v[i].y * ht[i].y + v[i].z * ht[i].z + v[i].w * ht[i].w;
#pragma unroll
        for (int off = 16; off > 0; off >>= 1) d += __shfl_xor_sync(0xffffffffu, d, off);
        if (lane == 0) g_logits[b * S + s] = d;
        float mn = fmaxf(m, d);
        float sc = __expf(m - mn);
        float w  = __expf(d - mn);
        l = l * sc + w;
#pragma unroll
        for (int i = 0; i < 8; i++) {
            acc[i].x = acc[i].x * sc + w * v[i].x;
            acc[i].y = acc[i].y * sc + w * v[i].y;
            acc[i].z = acc[i].z * sc + w * v[i].z;
            acc[i].w = acc[i].w * sc + w * v[i].w;
        }
        m = mn;
    }
#pragma unroll
    for (int i = 0; i < 8; i++) *(float4*)&accS[warp][i * 128 + lane * 4] = acc[i];
    if (lane == 0) { wm[warp] = m; wl[warp] = l; }
    __syncthreads();
    if (tid == 0) {
        float M = -1e30f;
        for (int w0 = 0; w0 < 8; w0++) M = fmaxf(M, wm[w0]);
        float L = 0.f;
        for (int w0 = 0; w0 < 8; w0++) { float f = __expf(wm[w0] - M); wf[w0] = f; L += wl[w0] * f; }
        g_part_m[b * NSPLIT + sp] = M;
        g_part_l[b * NSPLIT + sp] = L;
    }
    __syncthreads();
    for (int j = tid; j < H; j += 256) {
        float s = 0.f;
#pragma unroll
        for (int w0 = 0; w0 < 8; w0++) s += accS[w0][j] * wf[w0];
        g_part_acc[((size_t)b * NSPLIT + sp) * H + j] = s;
    }
}

// combine split partials -> c_enc (into A3 + hist); write softmax probs
__global__ __launch_bounds__(256)
void combine_step(int t, float* __restrict__ out)
{
    int b = blockIdx.x, tid = threadIdx.x;
    __shared__ float fP[NSPLIT];
    __shared__ float sM, sL;
    if (tid == 0) {
        float M = -1e30f;
        for (int p = 0; p < NSPLIT; p++) M = fmaxf(M, g_part_m[b * NSPLIT + p]);
        float L = 0.f;
        for (int p = 0; p < NSPLIT; p++) {
            float f = __expf(g_part_m[b * NSPLIT + p] - M);
            fP[p] = f;
            L += g_part_l[b * NSPLIT + p] * f;
        }
        sM = M; sL = L;
    }
    __syncthreads();
    float invL = 1.f / sL;
    size_t hrow = ((size_t)b * T + t) * KREC;
    for (int j = tid; j < H; j += 256) {
        float ce = 0.f;
#pragma unroll
        for (int p = 0; p < NSPLIT; p++)
            ce += g_part_acc[((size_t)b * NSPLIT + p) * H + j] * fP[p];
        float v = ce * invL;
        __nv_bfloat16 vh, vl;
        split2(v, vh, vl);
        g_A3_h[b * K3 + j] = vh;  g_A3_l[b * K3 + j] = vl;
        g_hist_h[hrow + j] = vh;  g_hist_l[hrow + j] = vl;
    }
    float M = sM;
    for (int s = tid; s < S; s += 256)
        out[OFF_ATTN + (size_t)t * B * S + (size_t)b * S + s] =
            __expf(g_logits[b * S + s] - M) * invL;
}

// batched p_gen for all (b,t): sigmoid([x, h, c_enc] @ W_pt.T + b_pt)
__global__ __launch_bounds__(256)
void pgen_all(const float* __restrict__ input_, const float* __restrict__ W_pt,
              const float* __restrict__ b_pt, float* __restrict__ out)
{
    int t = blockIdx.x, b = blockIdx.y;
    int tid = threadIdx.x;
    const float* xk = input_ + ((size_t)b * T + t) * IN_DIM;
    size_t hrow = ((size_t)b * T + t) * KREC;
    float s = 0.f;
    for (int k = tid; k < IN_DIM; k += 256) s += W_pt[k] * xk[k];
    for (int k = tid; k < H; k += 256)
        s += W_pt[IN_DIM + k] * join2(g_hist_h[hrow + H + k], g_hist_l[hrow + H + k]);
    for (int k = tid; k < H; k += 256)
        s += W_pt[IN_DIM + H + k] * join2(g_hist_h[hrow + k], g_hist_l[hrow + k]);
    __shared__ float red[256];
    red[tid] = s;
    __syncthreads();
    for (int st = 128; st > 0; st >>= 1) {
        if (tid < st) red[tid] += red[tid + st];
        __syncthreads();
    }
    if (tid == 0) {
        float p = 1.f / (1.f + expf(-(red[0] + b_pt[0])));
        out[OFF_P + (size_t)b * T + t] = p;
    }
}

__global__ void final_kernel(const float* __restrict__ past_attn_in,
                             const float* __restrict__ past_dehy_in,
                             float* __restrict__ out)
{
    int idx = blockIdx.x * blockDim.x + threadIdx.x;
    if (idx < B * H) {
        out[OFF_H + idx] = g_h[idx];
        out[OFF_C + idx] = g_c[idx];
        int b = idx >> 10, n = idx & 1023;
        out[OFF_HA + idx] = out[OFF_OUT + ((size_t)b * T + (T - 1)) * H + n];
        out[OFF_DEHY + idx] = past_dehy_in[idx];
    }
    if (idx < B * S) out[OFF_PATTN + idx] = past_attn_in[idx];
    if (idx == 0) out[OFF_LOSS] = 0.f;
}

// ============================================================
extern "C" void kernel_launch(void* const* d_in, const int* in_sizes, int n_in,
                              void* d_out, int out_size)
{
    int base = (in_sizes[0] == 1) ? 1 : 0;
    const float* input_    = (const float*)d_in[base + 0];
    const float* hidden_h  = (const float*)d_in[base + 1];
    const float* hidden_c  = (const float*)d_in[base + 2];
    const float* h_attn    = (const float*)d_in[base + 3];
    const float* enc       = (const float*)d_in[base + 4];
    const float* past_attn = (const float*)d_in[base + 5];
    const float* past_dehy = (const float*)d_in[base + 7];
    const float* W_ih  = (const float*)d_in[base + 8];
    const float* b_ih  = (const float*)d_in[base + 9];
    const float* W_hh  = (const float*)d_in[base + 10];
    const float* b_hh  = (const float*)d_in[base + 11];
    const float* W_attn= (const float*)d_in[base + 12];
    const float* W_out = (const float*)d_in[base + 13];
    const float* b_out = (const float*)d_in[base + 14];
    const float* W_pt  = (const float*)d_in[base + 15];
    const float* b_pt  = (const float*)d_in[base + 16];
    float* out = (float*)d_out;

    float *pXg, *pbg, *pGates, *pHtil, *pWfold32;
    __nv_bfloat16 *pWrh, *pWrl, *pWbigh, *pWbigl, *pWath, *pWatl;
    __nv_bfloat16 *pWouth, *pWoutl, *pWoutTh, *pWoutTl, *pWihh, *pWihl;
    __nv_bfloat16 *pInh, *pInl, *pArech, *pArecl, *pA3h, *pA3l;
    __nv_bfloat16 *pHisth, *pHistl, *pHh, *pHl;
    cudaGetSymbolAddress((void**)&pXg,     g_Xg);
    cudaGetSymbolAddress((void**)&pbg,     g_biasg);
    cudaGetSymbolAddress((void**)&pGates,  g_gates_part);
    cudaGetSymbolAddress((void**)&pHtil,   g_htil_part);
    cudaGetSymbolAddress((void**)&pWfold32,g_Wfold32);
    cudaGetSymbolAddress((void**)&pWrh,    g_Wr_h);
    cudaGetSymbolAddress((void**)&pWrl,    g_Wr_l);
    cudaGetSymbolAddress((void**)&pWbigh,  g_Wbig_h);
    cudaGetSymbolAddress((void**)&pWbigl,  g_Wbig_l);
    cudaGetSymbolAddress((void**)&pWath,   g_Wat_h);
    cudaGetSymbolAddress((void**)&pWatl,   g_Wat_l);
    cudaGetSymbolAddress((void**)&pWouth,  g_Wout_h);
    cudaGetSymbolAddress((void**)&pWoutl,  g_Wout_l);
    cudaGetSymbolAddress((void**)&pWoutTh, g_WoutT_h);
    cudaGetSymbolAddress((void**)&pWoutTl, g_WoutT_l);
    cudaGetSymbolAddress((void**)&pWihh,   g_Wih_h);
    cudaGetSymbolAddress((void**)&pWihl,   g_Wih_l);
    cudaGetSymbolAddress((void**)&pInh,    g_in_h);
    cudaGetSymbolAddress((void**)&pInl,    g_in_l);
    cudaGetSymbolAddress((void**)&pArech,  g_Arec_h);
    cudaGetSymbolAddress((void**)&pArecl,  g_Arec_l);
    cudaGetSymbolAddress((void**)&pA3h,    g_A3_h);
    cudaGetSymbolAddress((void**)&pA3l,    g_A3_l);
    cudaGetSymbolAddress((void**)&pHisth,  g_hist_h);
    cudaGetSymbolAddress((void**)&pHistl,  g_hist_l);
    cudaGetSymbolAddress((void**)&pHh,     g_h_h);
    cudaGetSymbolAddress((void**)&pHl,     g_h_l);

    static bool attr_set = false;
    if (!attr_set) {
        cudaFuncSetAttribute(hgemm_tn, cudaFuncAttributeMaxDynamicSharedMemorySize,
                             SMEM_BYTES);
        attr_set = true;
    }

    prep_kernel<<<2048, 256>>>(W_ih, W_hh, b_ih, b_hh, W_attn, W_out, b_out, input_);
    // Wfold = Wr_a @ W_out : M=G4, N=KREC, K=H (A = Wr cols 0..H with lda=KREC)
    hgemm_tn<<<dim3(KREC / 128, G4 / 128, 1), 256, SMEM_BYTES>>>(
        pWrh, pWrl, KREC, pWoutTh, pWoutTl, H, pWfold32, G4, KREC, H, nullptr);
    pack_wbig<<<2048, 256>>>();
    init_kernel<<<(B * H + 255) / 256, 256>>>(hidden_h, hidden_c, h_attn);

    // Xg = input_ @ W_ih[:, :IN].T + (b_ih + b_hh)
    hgemm_tn<<<dim3(G4 / 128, (B * T) / 128, 1), 256, SMEM_BYTES>>>(
        pInh, pInl, IN_DIM, pWihh, pWihl, IN_DIM, pXg, B * T, G4, IN_DIM, pbg);

    for (int t = 0; t < T; t++) {
        if (t == 0) {
            // gates partial: [ha0, h0] @ Wr.T
            hgemm_tn<<<dim3(G4 / 128, 1, SK_GATES), 256, SMEM_BYTES>>>(
                pArech, pArecl, KREC, pWrh, pWrl, KREC, pGates, B, G4,
                KREC / SK_GATES, nullptr);
        } else {
            // folded gates partial: [c_enc, h, h] @ Wbig.T
            hgemm_tn<<<dim3(G4 / 128, 1, SK_GATES), 256, SMEM_BYTES>>>(
                pA3h, pA3l, K3, pWbigh, pWbigl, K3, pGates, B, G4,
                K3 / SK_GATES, nullptr);
        }
        lstm_step<<<(B * H) / 256, 256>>>(t);
        // h~ = h @ W_attn
        hgemm_tn<<<dim3(H / 128, 1, SK_HTIL), 256, SMEM_BYTES>>>(
            pHh, pHl, H, pWath, pWatl, H, pHtil, B, H, H / SK_HTIL, nullptr);
        flash_step<<<dim3(B, NSPLIT), 256>>>(enc);
        combine_step<<<B, 256>>>(t, out);
    }

    // batched output_: ha_all = hist @ W_out.T + b_out (rows = b*T+t)
    hgemm_tn<<<dim3(H / 128, (B * T) / 128, 1), 256, SMEM_BYTES>>>(
        pHisth, pHistl, KREC, pWouth, pWoutl, KREC, out + OFF_OUT, B * T, H,
        KREC, b_out);
    pgen_all<<<dim3(T, B), 256>>>(input_, W_pt, b_pt, out);
    final_kernel<<<(B * H + 255) / 256, 256>>>(past_attn, past_dehy, out);
}

// round 6
// speedup vs baseline: 1.1861x; 1.1861x over previous
#include <cuda_runtime.h>
#include <cuda_bf16.h>
#include <math.h>

#define B 128
#define T 32
#define S 512
#define H 1024
#define IN_DIM 1024
#define G4 4096          // 4*H
#define KREC 2048        // H (ha) + H (h)

#define SK_GATES 4
#define SK_HTIL 16
#define SK_WOUT 16
#define NSPLIT 4

// ---- output offsets (flattened tuple, fp32) ----
#define OFF_OUT   0ull
#define OFF_H     4194304ull
#define OFF_C     4325376ull
#define OFF_HA    4456448ull
#define OFF_ATTN  4587520ull
#define OFF_PATTN 6684672ull
#define OFF_P     6750208ull
#define OFF_DEHY  6754304ull
#define OFF_LOSS  6885376ull

// ---- scratch ----
__device__ float g_Xg[(size_t)B * T * G4];
__device__ float g_biasg[G4];
__device__ float g_gates_part[SK_GATES * B * G4];
__device__ float g_htil_part[SK_HTIL * B * H];
__device__ float g_wout_part[SK_WOUT * B * H];
__device__ float g_Arec[B * KREC];                // fp32 ha (final output)
__device__ float g_h[B * H];
__device__ float g_c[B * H];
__device__ float g_logits[B * S];
__device__ float g_part_acc[B * NSPLIT * H];
__device__ float g_part_m[B * NSPLIT];
__device__ float g_part_l[B * NSPLIT];
__device__ int   g_cnt[B];                        // zero-init; self-resetting

// bf16 hi/lo split weights (built once in prep)
__device__ __nv_bfloat16 g_Wr_h[(size_t)G4 * KREC];
__device__ __nv_bfloat16 g_Wr_l[(size_t)G4 * KREC];
__device__ __nv_bfloat16 g_Wat_h[H * H];
__device__ __nv_bfloat16 g_Wat_l[H * H];
__device__ __nv_bfloat16 g_Wout_h[H * KREC];
__device__ __nv_bfloat16 g_Wout_l[H * KREC];
__device__ __nv_bfloat16 g_Wih_h[(size_t)G4 * IN_DIM];
__device__ __nv_bfloat16 g_Wih_l[(size_t)G4 * IN_DIM];
__device__ __nv_bfloat16 g_in_h[(size_t)B * T * IN_DIM];
__device__ __nv_bfloat16 g_in_l[(size_t)B * T * IN_DIM];
// bf16 hi/lo activations
__device__ __nv_bfloat16 g_Arec_h[B * KREC];
__device__ __nv_bfloat16 g_Arec_l[B * KREC];
__device__ __nv_bfloat16 g_Aout_h[B * KREC];
__device__ __nv_bfloat16 g_Aout_l[B * KREC];
__device__ __nv_bfloat16 g_h_h[B * H];
__device__ __nv_bfloat16 g_h_l[B * H];

__device__ __forceinline__ void split2(float x, __nv_bfloat16& hi, __nv_bfloat16& lo)
{
    hi = __float2bfloat16(x);
    lo = __float2bfloat16(x - __bfloat162float(hi));
}

// ============================================================
// Tensor-core GEMM: C = A @ W.T with bf16x3 split.
// ============================================================
#define SKP  40
#define TILE (128 * SKP)
#define SMEM_BYTES (2 * 4 * TILE * 2)

__device__ __forceinline__ void ldsm4(unsigned* r, unsigned addr)
{
    asm volatile("ldmatrix.sync.aligned.m8n8.x4.shared.b16 {%0,%1,%2,%3}, [%4];"
                 : "=r"(r[0]), "=r"(r[1]), "=r"(r[2]), "=r"(r[3]) : "r"(addr));
}
__device__ __forceinline__ void mma16816(float* d, const unsigned* a, const unsigned* b)
{
    asm volatile("mma.sync.aligned.m16n8k16.row.col.f32.bf16.bf16.f32 "
                 "{%0,%1,%2,%3}, {%4,%5,%6,%7}, {%8,%9}, {%0,%1,%2,%3};"
                 : "+f"(d[0]), "+f"(d[1]), "+f"(d[2]), "+f"(d[3])
                 : "r"(a[0]), "r"(a[1]), "r"(a[2]), "r"(a[3]), "r"(b[0]), "r"(b[1]));
}
#define CP16(dst, src) \
    asm volatile("cp.async.cg.shared.global [%0], [%1], 16;" :: "r"(dst), "l"(src))
#define CP_COMMIT() asm volatile("cp.async.commit_group;")
#define CP_WAIT(n)  asm volatile("cp.async.wait_group %0;" :: "n"(n))

__global__ __launch_bounds__(256)
void hgemm_tn(const __nv_bfloat16* __restrict__ Ah, const __nv_bfloat16* __restrict__ Al,
              int lda,
              const __nv_bfloat16* __restrict__ Wh, const __nv_bfloat16* __restrict__ Wl,
              int ldw,
              float* __restrict__ Cpart, int M, int N, int Kslice,
              const float* __restrict__ bias)
{
    extern __shared__ __nv_bfloat16 smem[];
    const int bn = blockIdx.x, bm = blockIdx.y, bz = blockIdx.z;
    Ah += (size_t)bm * 128 * lda + (size_t)bz * Kslice;
    Al += (size_t)bm * 128 * lda + (size_t)bz * Kslice;
    Wh += (size_t)bn * 128 * ldw + (size_t)bz * Kslice;
    Wl += (size_t)bn * 128 * ldw + (size_t)bz * Kslice;
    float* C = Cpart + (size_t)bz * M * N + (size_t)bm * 128 * N + (size_t)bn * 128;

    const int tid = threadIdx.x;
    const int warp = tid >> 5, lane = tid & 31;
    const int wm = (warp >> 2) * 64;
    const int wn = (warp & 3) * 32;

    const unsigned sbase = (unsigned)__cvta_generic_to_shared(smem);

    float acc[4][4][4];
#pragma unroll
    for (int i = 0; i < 4; i++)
#pragma unroll
        for (int j = 0; j < 4; j++)
#pragma unroll
            for (int q = 0; q < 4; q++) acc[i][j][q] = 0.f;

    const int nIter = Kslice >> 5;

    auto load_stage = [&](int stage, int ko) {
        unsigned sb = sbase + (unsigned)(stage * 4 * TILE) * 2;
#pragma unroll
        for (int i = 0; i < 2; i++) {
            int idx = i * 256 + tid;
            int row = idx >> 2, ch = (idx & 3) * 8;
            unsigned doff = (unsigned)(row * SKP + ch) * 2;
            size_t ga = (size_t)row * lda + ko + ch;
            size_t gw = (size_t)row * ldw + ko + ch;
            CP16(sb + doff,                         Ah + ga);
            CP16(sb + (unsigned)TILE * 2 + doff,    Al + ga);
            CP16(sb + (unsigned)TILE * 4 + doff,    Wh + gw);
            CP16(sb + (unsigned)TILE * 6 + doff,    Wl + gw);
        }
    };

    load_stage(0, 0);
    CP_COMMIT();
    if (nIter > 1) { load_stage(1, 32); CP_COMMIT(); }

    const int rA = lane & 15;
    const int kA = (lane >> 4) * 8;
    const int rB = (lane & 7) + ((lane & 16) ? 8 : 0);
    const int kB = (lane & 8);

    for (int it = 0; it < nIter; it++) {
        if (it + 1 < nIter) { CP_WAIT(1); } else { CP_WAIT(0); }
        __syncthreads();

        unsigned base = sbase + (unsigned)((it & 1) * 4 * TILE) * 2;
#pragma unroll
        for (int k16 = 0; k16 < 32; k16 += 16) {
            unsigned ah[4][4], al[4][4], bh[4][2], bl[4][2];
#pragma unroll
            for (int mt = 0; mt < 4; mt++) {
                unsigned ad = base + (unsigned)((wm + mt * 16 + rA) * SKP + k16 + kA) * 2;
                ldsm4(ah[mt], ad);
                ldsm4(al[mt], ad + (unsigned)TILE * 2);
            }
#pragma unroll
            for (int np = 0; np < 2; np++) {
                unsigned bd = base + (unsigned)TILE * 4 +
                              (unsigned)((wn + np * 16 + rB) * SKP + k16 + kB) * 2;
                unsigned r[4];
                ldsm4(r, bd);
                bh[np * 2][0] = r[0]; bh[np * 2][1] = r[1];
                bh[np * 2 + 1][0] = r[2]; bh[np * 2 + 1][1] = r[3];
                ldsm4(r, bd + (unsigned)TILE * 2);
                bl[np * 2][0] = r[0]; bl[np * 2][1] = r[1];
                bl[np * 2 + 1][0] = r[2]; bl[np * 2 + 1][1] = r[3];
            }
#pragma unroll
            for (int mt = 0; mt < 4; mt++)
#pragma unroll
                for (int nt = 0; nt < 4; nt++) {
                    mma16816(acc[mt][nt], ah[mt], bh[nt]);
                    mma16816(acc[mt][nt], al[mt], bh[nt]);
                    mma16816(acc[mt][nt], ah[mt], bl[nt]);
                }
        }
        __syncthreads();
        if (it + 2 < nIter) { load_stage(it & 1, (it + 2) * 32); CP_COMMIT(); }
    }

    const int er = lane >> 2;
    const int ec = (lane & 3) * 2;
#pragma unroll
    for (int mt = 0; mt < 4; mt++)
#pragma unroll
        for (int nt = 0; nt < 4; nt++) {
            int r0 = wm + mt * 16 + er;
            int c0 = wn + nt * 8 + ec;
            float b0 = 0.f, b1 = 0.f;
            if (bias != nullptr) {
                b0 = bias[bn * 128 + c0];
                b1 = bias[bn * 128 + c0 + 1];
            }
            float* p0 = C + (size_t)r0 * N + c0;
            float* p1 = C + (size_t)(r0 + 8) * N + c0;
            p0[0] = acc[mt][nt][0] + b0;
            p0[1] = acc[mt][nt][1] + b1;
            p1[0] = acc[mt][nt][2] + b0;
            p1[1] = acc[mt][nt][3] + b1;
        }
}

// ============================================================
// Setup kernels
// ============================================================
__global__ void prep_kernel(const float* __restrict__ W_ih, const float* __restrict__ W_hh,
                            const float* __restrict__ b_ih, const float* __restrict__ b_hh,
                            const float* __restrict__ W_attn, const float* __restrict__ W_out,
                            const float* __restrict__ input_)
{
    size_t stride = (size_t)gridDim.x * blockDim.x;
    size_t start = (size_t)blockIdx.x * blockDim.x + threadIdx.x;
    for (size_t idx = start; idx < (size_t)G4 * KREC; idx += stride) {
        int n = (int)(idx >> 11);
        int k = (int)(idx & 2047);
        float v = (k < H) ? W_ih[(size_t)n * KREC + IN_DIM + k]
                          : W_hh[(size_t)n * H + (k - H)];
        split2(v, g_Wr_h[idx], g_Wr_l[idx]);
    }
    for (size_t idx = start; idx < (size_t)H * H; idx += stride) {
        int n = (int)(idx >> 10), k = (int)(idx & 1023);
        split2(W_attn[(size_t)k * H + n], g_Wat_h[idx], g_Wat_l[idx]);
    }
    for (size_t idx = start; idx < (size_t)H * KREC; idx += stride)
        split2(W_out[idx], g_Wout_h[idx], g_Wout_l[idx]);
    for (size_t idx = start; idx < (size_t)G4 * IN_DIM; idx += stride) {
        int n = (int)(idx >> 10), k = (int)(idx & 1023);
        split2(W_ih[(size_t)n * KREC + k], g_Wih_h[idx], g_Wih_l[idx]);
    }
    for (size_t idx = start; idx < (size_t)B * T * IN_DIM; idx += stride)
        split2(input_[idx], g_in_h[idx], g_in_l[idx]);
    for (size_t idx = start; idx < (size_t)G4; idx += stride)
        g_biasg[idx] = b_ih[idx] + b_hh[idx];
}

__global__ void init_kernel(const float* __restrict__ hh, const float* __restrict__ hc,
                            const float* __restrict__ ha)
{
    int idx = blockIdx.x * blockDim.x + threadIdx.x;
    if (idx < B * H) {
        int b = idx >> 10, n = idx & 1023;
        g_h[idx] = hh[idx];
        g_c[idx] = hc[idx];
        split2(ha[idx], g_Arec_h[b * KREC + n], g_Arec_l[b * KREC + n]);
        split2(hh[idx], g_Arec_h[b * KREC + H + n], g_Arec_l[b * KREC + H + n]);
        if (idx < B) g_cnt[idx] = 0;
    }
}

// ============================================================
// LSTM cell: reduce gate partials + Xg, update h/c
// ============================================================
__global__ void lstm_step(int t)
{
    int idx = blockIdx.x * blockDim.x + threadIdx.x;   // B*H
    int b = idx >> 10, n = idx & 1023;
    size_t row = ((size_t)b * T + t) * G4;
    float gi = g_Xg[row + n];
    float gf = g_Xg[row + H + n];
    float gg = g_Xg[row + 2 * H + n];
    float go = g_Xg[row + 3 * H + n];
#pragma unroll
    for (int p = 0; p < SK_GATES; p++) {
        const float* gp = g_gates_part + (size_t)p * B * G4 + (size_t)b * G4;
        gi += gp[n]; gf += gp[H + n]; gg += gp[2 * H + n]; go += gp[3 * H + n];
    }
    float i_ = 1.f / (1.f + expf(-gi));
    float f_ = 1.f / (1.f + expf(-gf));
    float g_ = tanhf(gg);
    float o_ = 1.f / (1.f + expf(-go));
    float c_new = f_ * g_c[idx] + i_ * g_;
    float h_new = o_ * tanhf(c_new);
    g_c[idx] = c_new;
    g_h[idx] = h_new;
    __nv_bfloat16 hH, hL;
    split2(h_new, hH, hL);
    g_h_h[idx] = hH; g_h_l[idx] = hL;
    g_Arec_h[b * KREC + H + n] = hH; g_Arec_l[b * KREC + H + n] = hL;
    g_Aout_h[b * KREC + H + n] = hH; g_Aout_l[b * KREC + H + n] = hL;
}

// ============================================================
// Flash attention split + fused last-block combine/attn/p_gen.
// grid (B, NSPLIT), 256 threads. Last finishing block per b does
// the combine (deterministic: identical math regardless of which).
// ============================================================
__global__ __launch_bounds__(256)
void flash_step(int t, const float* __restrict__ enc,
                const float* __restrict__ input_, const float* __restrict__ W_pt,
                const float* __restrict__ b_pt, float* __restrict__ out)
{
    int b = blockIdx.x, sp = blockIdx.y;
    __shared__ float htil[H];                 // reused as c_enc in the tail
    __shared__ float accS[8][1024];           // accS[0][0..255] reused as red
    __shared__ float wm[8], wl[8], wf[8];
    __shared__ float fP[NSPLIT];
    __shared__ float sM, sL;
    __shared__ int   sLast;
    int tid = threadIdx.x;

    // reduce split-K partials of h~ = h @ W_attn
    for (int j = tid; j < H; j += 256) {
        float s = 0.f;
#pragma unroll
        for (int p = 0; p < SK_HTIL; p++) s += g_htil_part[(size_t)p * B * H + b * H + j];
        htil[j] = s;
    }
    __syncthreads();

    int warp = tid >> 5, lane = tid & 31;
    float m = -1e30f, l = 0.f;
    float4 acc[8];
#pragma unroll
    for (int i = 0; i < 8; i++) acc[i] = make_float4(0.f, 0.f, 0.f, 0.f);

    float4 ht[8];
#pragma unroll
    for (int i = 0; i < 8; i++) ht[i] = *(const float4*)&htil[i * 128 + lane * 4];

    const float* encb = enc + (size_t)b * S * H;
    int s0 = sp * 128 + warp * 16;
    for (int si = 0; si < 16; si++) {
        int s = s0 + si;
        const float4* er = (const float4*)(encb + (size_t)s * H) + lane;
        float4 v[8];
#pragma unroll
        for (int i = 0; i < 8; i++) v[i] = er[i * 32];
        float d = 0.f;
#pragma unroll
        for (int i = 0; i < 8; i++)
            d += v[i].x * ht[i].x + v[i].y * ht[i].y + v[i].z * ht[i].z + v[i].w * ht[i].w;
#pragma unroll
        for (int off = 16; off > 0; off >>= 1) d += __shfl_xor_sync(0xffffffffu, d, off);
        if (lane == 0) g_logits[b * S + s] = d;
        float mn = fmaxf(m, d);
        float sc = __expf(m - mn);
        float w  = __expf(d - mn);
        l = l * sc + w;
#pragma unroll
        for (int i = 0; i < 8; i++) {
            acc[i].x = acc[i].x * sc + w * v[i].x;
            acc[i].y = acc[i].y * sc + w * v[i].y;
            acc[i].z = acc[i].z * sc + w * v[i].z;
            acc[i].w = acc[i].w * sc + w * v[i].w;
        }
        m = mn;
    }
#pragma unroll
    for (int i = 0; i < 8; i++) *(float4*)&accS[warp][i * 128 + lane * 4] = acc[i];
    if (lane == 0) { wm[warp] = m; wl[warp] = l; }
    __syncthreads();
    if (tid == 0) {
        float M = -1e30f;
        for (int w0 = 0; w0 < 8; w0++) M = fmaxf(M, wm[w0]);
        float L = 0.f;
        for (int w0 = 0; w0 < 8; w0++) { float f = __expf(wm[w0] - M); wf[w0] = f; L += wl[w0] * f; }
        g_part_m[b * NSPLIT + sp] = M;
        g_part_l[b * NSPLIT + sp] = L;
    }
    __syncthreads();
    for (int j = tid; j < H; j += 256) {
        float s = 0.f;
#pragma unroll
        for (int w0 = 0; w0 < 8; w0++) s += accS[w0][j] * wf[w0];
        g_part_acc[((size_t)b * NSPLIT + sp) * H + j] = s;
    }

    // ---- publish partials, elect last block ----
    __threadfence();
    __syncthreads();
    if (tid == 0) {
        int old = atomicAdd(&g_cnt[b], 1);
        sLast = (old == NSPLIT - 1);
        if (sLast) { g_cnt[b] = 0; __threadfence(); }
    }
    __syncthreads();
    if (!sLast) return;

    // ---- tail: combine + attn write + p_gen (one block per b) ----
    if (tid == 0) {
        float M = -1e30f;
        for (int p = 0; p < NSPLIT; p++) M = fmaxf(M, g_part_m[b * NSPLIT + p]);
        float L = 0.f;
        for (int p = 0; p < NSPLIT; p++) {
            float f = __expf(g_part_m[b * NSPLIT + p] - M);
            fP[p] = f;
            L += g_part_l[b * NSPLIT + p] * f;
        }
        sM = M; sL = L;
    }
    __syncthreads();
    float invL = 1.f / sL;
    for (int j = tid; j < H; j += 256) {
        float ce = 0.f;
#pragma unroll
        for (int p = 0; p < NSPLIT; p++)
            ce += g_part_acc[((size_t)b * NSPLIT + p) * H + j] * fP[p];
        float v = ce * invL;
        htil[j] = v;   // reuse as c_enc
        split2(v, g_Aout_h[b * KREC + j], g_Aout_l[b * KREC + j]);
    }
    float M = sM;
    for (int s = tid; s < S; s += 256)
        out[OFF_ATTN + (size_t)t * B * S + (size_t)b * S + s] =
            __expf(g_logits[b * S + s] - M) * invL;
    __syncthreads();

    // p_gen = sigmoid([x_k, h, c_enc] @ W_pt.T + b_pt)
    const float* xk = input_ + ((size_t)b * T + t) * IN_DIM;
    float s = 0.f;
    for (int k = tid; k < IN_DIM; k += 256) s += W_pt[k] * xk[k];
    for (int k = tid; k < H; k += 256)      s += W_pt[IN_DIM + k] * g_h[b * H + k];
    for (int k = tid; k < H; k += 256)      s += W_pt[IN_DIM + H + k] * htil[k];
    float* red = &accS[0][0];
    red[tid] = s;
    __syncthreads();
    for (int st = 128; st > 0; st >>= 1) {
        if (tid < st) red[tid] += red[tid + st];
        __syncthreads();
    }
    if (tid == 0) {
        float p = 1.f / (1.f + expf(-(red[0] + b_pt[0])));
        out[OFF_P + (size_t)b * T + t] = p;
    }
}

// ha = [c_enc, h] @ W_out.T + b_out  (sum split-K partials); write output_
__global__ void haepi_step(int t, float* __restrict__ out, const float* __restrict__ b_out)
{
    int idx = blockIdx.x * blockDim.x + threadIdx.x;   // B*H
    int b = idx >> 10, n = idx & 1023;
    float v = b_out[n];
#pragma unroll
    for (int p = 0; p < SK_WOUT; p++) v += g_wout_part[(size_t)p * B * H + idx];
    g_Arec[b * KREC + n] = v;
    split2(v, g_Arec_h[b * KREC + n], g_Arec_l[b * KREC + n]);
    out[OFF_OUT + ((size_t)b * T + t) * H + n] = v;
}

__global__ void final_kernel(const float* __restrict__ past_attn_in,
                             const float* __restrict__ past_dehy_in,
                             float* __restrict__ out)
{
    int idx = blockIdx.x * blockDim.x + threadIdx.x;
    if (idx < B * H) {
        out[OFF_H + idx] = g_h[idx];
        out[OFF_C + idx] = g_c[idx];
        int b = idx >> 10, n = idx & 1023;
        out[OFF_HA + idx] = g_Arec[b * KREC + n];
        out[OFF_DEHY + idx] = past_dehy_in[idx];
    }
    if (idx < B * S) out[OFF_PATTN + idx] = past_attn_in[idx];
    if (idx == 0) out[OFF_LOSS] = 0.f;
}

// ============================================================
extern "C" void kernel_launch(void* const* d_in, const int* in_sizes, int n_in,
                              void* d_out, int out_size)
{
    int base = (in_sizes[0] == 1) ? 1 : 0;
    const float* input_    = (const float*)d_in[base + 0];
    const float* hidden_h  = (const float*)d_in[base + 1];
    const float* hidden_c  = (const float*)d_in[base + 2];
    const float* h_attn    = (const float*)d_in[base + 3];
    const float* enc       = (const float*)d_in[base + 4];
    const float* past_attn = (const float*)d_in[base + 5];
    const float* past_dehy = (const float*)d_in[base + 7];
    const float* W_ih  = (const float*)d_in[base + 8];
    const float* b_ih  = (const float*)d_in[base + 9];
    const float* W_hh  = (const float*)d_in[base + 10];
    const float* b_hh  = (const float*)d_in[base + 11];
    const float* W_attn= (const float*)d_in[base + 12];
    const float* W_out = (const float*)d_in[base + 13];
    const float* b_out = (const float*)d_in[base + 14];
    const float* W_pt  = (const float*)d_in[base + 15];
    const float* b_pt  = (const float*)d_in[base + 16];
    float* out = (float*)d_out;

    float *pXg, *pbg, *pGates, *pHtil, *pWoutp;
    __nv_bfloat16 *pWrh, *pWrl, *pWath, *pWatl, *pWouth, *pWoutl, *pWihh, *pWihl;
    __nv_bfloat16 *pInh, *pInl, *pArech, *pArecl, *pAouth, *pAoutl, *pHh, *pHl;
    cudaGetSymbolAddress((void**)&pXg,    g_Xg);
    cudaGetSymbolAddress((void**)&pbg,    g_biasg);
    cudaGetSymbolAddress((void**)&pGates, g_gates_part);
    cudaGetSymbolAddress((void**)&pHtil,  g_htil_part);
    cudaGetSymbolAddress((void**)&pWoutp, g_wout_part);
    cudaGetSymbolAddress((void**)&pWrh,   g_Wr_h);
    cudaGetSymbolAddress((void**)&pWrl,   g_Wr_l);
    cudaGetSymbolAddress((void**)&pWath,  g_Wat_h);
    cudaGetSymbolAddress((void**)&pWatl,  g_Wat_l);
    cudaGetSymbolAddress((void**)&pWouth, g_Wout_h);
    cudaGetSymbolAddress((void**)&pWoutl, g_Wout_l);
    cudaGetSymbolAddress((void**)&pWihh,  g_Wih_h);
    cudaGetSymbolAddress((void**)&pWihl,  g_Wih_l);
    cudaGetSymbolAddress((void**)&pInh,   g_in_h);
    cudaGetSymbolAddress((void**)&pInl,   g_in_l);
    cudaGetSymbolAddress((void**)&pArech, g_Arec_h);
    cudaGetSymbolAddress((void**)&pArecl, g_Arec_l);
    cudaGetSymbolAddress((void**)&pAouth, g_Aout_h);
    cudaGetSymbolAddress((void**)&pAoutl, g_Aout_l);
    cudaGetSymbolAddress((void**)&pHh,    g_h_h);
    cudaGetSymbolAddress((void**)&pHl,    g_h_l);

    static bool attr_set = false;
    if (!attr_set) {
        cudaFuncSetAttribute(hgemm_tn, cudaFuncAttributeMaxDynamicSharedMemorySize,
                             SMEM_BYTES);
        attr_set = true;
    }

    prep_kernel<<<2048, 256>>>(W_ih, W_hh, b_ih, b_hh, W_attn, W_out, input_);
    init_kernel<<<(B * H + 255) / 256, 256>>>(hidden_h, hidden_c, h_attn);

    // Xg = input_ @ W_ih[:, :IN].T + (b_ih + b_hh)
    hgemm_tn<<<dim3(G4 / 128, (B * T) / 128, 1), 256, SMEM_BYTES>>>(
        pInh, pInl, IN_DIM, pWihh, pWihl, IN_DIM, pXg, B * T, G4, IN_DIM, pbg);

    for (int t = 0; t < T; t++) {
        // gates partial: [ha, h] @ [W_ih[:,IN:], W_hh].T
        hgemm_tn<<<dim3(G4 / 128, 1, SK_GATES), 256, SMEM_BYTES>>>(
            pArech, pArecl, KREC, pWrh, pWrl, KREC, pGates, B, G4,
            KREC / SK_GATES, nullptr);
        lstm_step<<<(B * H) / 256, 256>>>(t);
        // h~ = h @ W_attn
        hgemm_tn<<<dim3(H / 128, 1, SK_HTIL), 256, SMEM_BYTES>>>(
            pHh, pHl, H, pWath, pWatl, H, pHtil, B, H, H / SK_HTIL, nullptr);
        flash_step<<<dim3(B, NSPLIT), 256>>>(t, enc, input_, W_pt, b_pt, out);
        // ha partial: [c_enc, h] @ W_out.T
        hgemm_tn<<<dim3(H / 128, 1, SK_WOUT), 256, SMEM_BYTES>>>(
            pAouth, pAoutl, KREC, pWouth, pWoutl, KREC, pWoutp, B, H,
            KREC / SK_WOUT, nullptr);
        haepi_step<<<(B * H) / 256, 256>>>(t, out, b_out);
    }
    final_kernel<<<(B * H + 255) / 256, 256>>>(past_attn, past_dehy, out);
}

// round 8
// speedup vs baseline: 1.2221x; 1.0304x over previous
#include <cuda_runtime.h>
#include <cuda_bf16.h>
#include <math.h>

#define B 128
#define T 32
#define S 512
#define H 1024
#define IN_DIM 1024
#define G4 4096          // 4*H
#define KREC 2048        // H (ha) + H (h)

#define SK_GATES 4
#define SK_HTIL 16
#define SK_WOUT 16
#define NSPLIT 4

// ---- output offsets (flattened tuple, fp32) ----
#define OFF_OUT   0ull
#define OFF_H     4194304ull
#define OFF_C     4325376ull
#define OFF_HA    4456448ull
#define OFF_ATTN  4587520ull
#define OFF_PATTN 6684672ull
#define OFF_P     6750208ull
#define OFF_DEHY  6754304ull
#define OFF_LOSS  6885376ull

// ---- scratch ----
__device__ float g_Xg[(size_t)B * T * G4];        // rows (b*T + t)
__device__ float g_biasg[G4];
__device__ float g_gates_part[SK_GATES * B * G4];
__device__ float g_htil_part[SK_HTIL * B * H];
__device__ float g_wout_part[SK_WOUT * B * H];
__device__ float g_Arec[B * KREC];                // fp32 ha (final output)
__device__ float g_h[B * H];
__device__ float g_c[B * H];
__device__ float g_logits[B * S];
__device__ float g_part_acc[B * NSPLIT * H];
__device__ float g_part_m[B * NSPLIT];
__device__ float g_part_l[B * NSPLIT];
__device__ int   g_cnt[B];                        // zero-init; self-resetting

// bf16 hi/lo split weights (built once in prep)
__device__ __nv_bfloat16 g_Wr_h[(size_t)G4 * KREC];
__device__ __nv_bfloat16 g_Wr_l[(size_t)G4 * KREC];
__device__ __nv_bfloat16 g_Wat_h[H * H];
__device__ __nv_bfloat16 g_Wat_l[H * H];
__device__ __nv_bfloat16 g_Wout_h[H * KREC];
__device__ __nv_bfloat16 g_Wout_l[H * KREC];
__device__ __nv_bfloat16 g_Wih_h[(size_t)G4 * IN_DIM];
__device__ __nv_bfloat16 g_Wih_l[(size_t)G4 * IN_DIM];
__device__ __nv_bfloat16 g_in_h[(size_t)B * T * IN_DIM];
__device__ __nv_bfloat16 g_in_l[(size_t)B * T * IN_DIM];
// bf16 hi/lo activations
__device__ __nv_bfloat16 g_Arec_h[B * KREC];
__device__ __nv_bfloat16 g_Arec_l[B * KREC];
__device__ __nv_bfloat16 g_Aout_h[B * KREC];
__device__ __nv_bfloat16 g_Aout_l[B * KREC];
__device__ __nv_bfloat16 g_h_h[B * H];
__device__ __nv_bfloat16 g_h_l[B * H];

__device__ __forceinline__ void split2(float x, __nv_bfloat16& hi, __nv_bfloat16& lo)
{
    hi = __float2bfloat16(x);
    lo = __float2bfloat16(x - __bfloat162float(hi));
}

// ============================================================
// Tensor-core GEMM: C = A @ W.T with bf16x3 split.
// 4-stage cp.async pipeline (prefetch distance 3), 1 sync/iter.
// ============================================================
#define SKP  40
#define TILE (128 * SKP)
#define NSTAGE 4
#define SMEM_BYTES (NSTAGE * 4 * TILE * 2)

__device__ __forceinline__ void ldsm4(unsigned* r, unsigned addr)
{
    asm volatile("ldmatrix.sync.aligned.m8n8.x4.shared.b16 {%0,%1,%2,%3}, [%4];"
                 : "=r"(r[0]), "=r"(r[1]), "=r"(r[2]), "=r"(r[3]) : "r"(addr));
}
__device__ __forceinline__ void mma16816(float* d, const unsigned* a, const unsigned* b)
{
    asm volatile("mma.sync.aligned.m16n8k16.row.col.f32.bf16.bf16.f32 "
                 "{%0,%1,%2,%3}, {%4,%5,%6,%7}, {%8,%9}, {%0,%1,%2,%3};"
                 : "+f"(d[0]), "+f"(d[1]), "+f"(d[2]), "+f"(d[3])
                 : "r"(a[0]), "r"(a[1]), "r"(a[2]), "r"(a[3]), "r"(b[0]), "r"(b[1]));
}
#define CP16(dst, src) \
    asm volatile("cp.async.cg.shared.global [%0], [%1], 16;" :: "r"(dst), "l"(src))
#define CP_COMMIT() asm volatile("cp.async.commit_group;")
#define CP_WAIT(n)  asm volatile("cp.async.wait_group %0;" :: "n"(n))

__global__ __launch_bounds__(256)
void hgemm_tn(const __nv_bfloat16* __restrict__ Ah, const __nv_bfloat16* __restrict__ Al,
              int lda,
              const __nv_bfloat16* __restrict__ Wh, const __nv_bfloat16* __restrict__ Wl,
              int ldw,
              float* __restrict__ Cpart, int M, int N, int Kslice,
              const float* __restrict__ bias)
{
    extern __shared__ __nv_bfloat16 smem[];
    const int bn = blockIdx.x, bm = blockIdx.y, bz = blockIdx.z;
    Ah += (size_t)bm * 128 * lda + (size_t)bz * Kslice;
    Al += (size_t)bm * 128 * lda + (size_t)bz * Kslice;
    Wh += (size_t)bn * 128 * ldw + (size_t)bz * Kslice;
    Wl += (size_t)bn * 128 * ldw + (size_t)bz * Kslice;
    float* C = Cpart + (size_t)bz * M * N + (size_t)bm * 128 * N + (size_t)bn * 128;

    const int tid = threadIdx.x;
    const int warp = tid >> 5, lane = tid & 31;
    const int wm = (warp >> 2) * 64;
    const int wn = (warp & 3) * 32;

    const unsigned sbase = (unsigned)__cvta_generic_to_shared(smem);

    float acc[4][4][4];
#pragma unroll
    for (int i = 0; i < 4; i++)
#pragma unroll
        for (int j = 0; j < 4; j++)
#pragma unroll
            for (int q = 0; q < 4; q++) acc[i][j][q] = 0.f;

    const int nIter = Kslice >> 5;

    auto load_stage = [&](int stage, int ko) {
        unsigned sb = sbase + (unsigned)(stage * 4 * TILE) * 2;
#pragma unroll
        for (int i = 0; i < 2; i++) {
            int idx = i * 256 + tid;
            int row = idx >> 2, ch = (idx & 3) * 8;
            unsigned doff = (unsigned)(row * SKP + ch) * 2;
            size_t ga = (size_t)row * lda + ko + ch;
            size_t gw = (size_t)row * ldw + ko + ch;
            CP16(sb + doff,                         Ah + ga);
            CP16(sb + (unsigned)TILE * 2 + doff,    Al + ga);
            CP16(sb + (unsigned)TILE * 4 + doff,    Wh + gw);
            CP16(sb + (unsigned)TILE * 6 + doff,    Wl + gw);
        }
    };

    // prologue: prefetch up to 3 stages
    for (int s = 0; s < 3 && s < nIter; s++) {
        load_stage(s, s * 32);
        CP_COMMIT();
    }

    const int rA = lane & 15;
    const int kA = (lane >> 4) * 8;
    const int rB = (lane & 7) + ((lane & 16) ? 8 : 0);
    const int kB = (lane & 8);

    for (int it = 0; it < nIter; it++) {
        if (it + 3 <= nIter) { CP_WAIT(2); } else { CP_WAIT(0); }
        __syncthreads();

        unsigned base = sbase + (unsigned)((it & (NSTAGE - 1)) * 4 * TILE) * 2;
#pragma unroll
        for (int k16 = 0; k16 < 32; k16 += 16) {
            unsigned ah[4][4], al[4][4], bh[4][2], bl[4][2];
#pragma unroll
            for (int mt = 0; mt < 4; mt++) {
                unsigned ad = base + (unsigned)((wm + mt * 16 + rA) * SKP + k16 + kA) * 2;
                ldsm4(ah[mt], ad);
                ldsm4(al[mt], ad + (unsigned)TILE * 2);
            }
#pragma unroll
            for (int np = 0; np < 2; np++) {
                unsigned bd = base + (unsigned)TILE * 4 +
                              (unsigned)((wn + np * 16 + rB) * SKP + k16 + kB) * 2;
                unsigned r[4];
                ldsm4(r, bd);
                bh[np * 2][0] = r[0]; bh[np * 2][1] = r[1];
                bh[np * 2 + 1][0] = r[2]; bh[np * 2 + 1][1] = r[3];
                ldsm4(r, bd + (unsigned)TILE * 2);
                bl[np * 2][0] = r[0]; bl[np * 2][1] = r[1];
                bl[np * 2 + 1][0] = r[2]; bl[np * 2 + 1][1] = r[3];
            }
#pragma unroll
            for (int mt = 0; mt < 4; mt++)
#pragma unroll
                for (int nt = 0; nt < 4; nt++) {
                    mma16816(acc[mt][nt], ah[mt], bh[nt]);
                    mma16816(acc[mt][nt], al[mt], bh[nt]);
                    mma16816(acc[mt][nt], ah[mt], bl[nt]);
                }
        }
        // buffer-reuse distance is 3 stages; top-of-iter sync suffices
        if (it + 3 < nIter) {
            load_stage((it + 3) & (NSTAGE - 1), (it + 3) * 32);
            CP_COMMIT();
        }
    }

    const int er = lane >> 2;
    const int ec = (lane & 3) * 2;
#pragma unroll
    for (int mt = 0; mt < 4; mt++)
#pragma unroll
        for (int nt = 0; nt < 4; nt++) {
            int r0 = wm + mt * 16 + er;
            int c0 = wn + nt * 8 + ec;
            float b0 = 0.f, b1 = 0.f;
            if (bias != nullptr) {
                b0 = bias[bn * 128 + c0];
                b1 = bias[bn * 128 + c0 + 1];
            }
            float* p0 = C + (size_t)r0 * N + c0;
            float* p1 = C + (size_t)(r0 + 8) * N + c0;
            p0[0] = acc[mt][nt][0] + b0;
            p0[1] = acc[mt][nt][1] + b1;
            p1[0] = acc[mt][nt][2] + b0;
            p1[1] = acc[mt][nt][3] + b1;
        }
}

// ============================================================
// Setup kernels
// ============================================================
__global__ void prep_kernel(const float* __restrict__ W_ih, const float* __restrict__ W_hh,
                            const float* __restrict__ b_ih, const float* __restrict__ b_hh,
                            const float* __restrict__ W_attn, const float* __restrict__ W_out,
                            const float* __restrict__ input_)
{
    size_t stride = (size_t)gridDim.x * blockDim.x;
    size_t start = (size_t)blockIdx.x * blockDim.x + threadIdx.x;
    for (size_t idx = start; idx < (size_t)G4 * KREC; idx += stride) {
        int n = (int)(idx >> 11);
        int k = (int)(idx & 2047);
        float v = (k < H) ? W_ih[(size_t)n * KREC + IN_DIM + k]
                          : W_hh[(size_t)n * H + (k - H)];
        split2(v, g_Wr_h[idx], g_Wr_l[idx]);
    }
    for (size_t idx = start; idx < (size_t)H * H; idx += stride) {
        int n = (int)(idx >> 10), k = (int)(idx & 1023);
        split2(W_attn[(size_t)k * H + n], g_Wat_h[idx], g_Wat_l[idx]);
    }
    for (size_t idx = start; idx < (size_t)H * KREC; idx += stride)
        split2(W_out[idx], g_Wout_h[idx], g_Wout_l[idx]);
    for (size_t idx = start; idx < (size_t)G4 * IN_DIM; idx += stride) {
        int n = (int)(idx >> 10), k = (int)(idx & 1023);
        split2(W_ih[(size_t)n * KREC + k], g_Wih_h[idx], g_Wih_l[idx]);
    }
    for (size_t idx = start; idx < (size_t)B * T * IN_DIM; idx += stride)
        split2(input_[idx], g_in_h[idx], g_in_l[idx]);
    for (size_t idx = start; idx < (size_t)G4; idx += stride)
        g_biasg[idx] = b_ih[idx] + b_hh[idx];
}

__global__ void init_kernel(const float* __restrict__ hh, const float* __restrict__ hc,
                            const float* __restrict__ ha)
{
    int idx = blockIdx.x * blockDim.x + threadIdx.x;
    if (idx < B * H) {
        int b = idx >> 10, n = idx & 1023;
        g_h[idx] = hh[idx];
        g_c[idx] = hc[idx];
        split2(ha[idx], g_Arec_h[b * KREC + n], g_Arec_l[b * KREC + n]);
        split2(hh[idx], g_Arec_h[b * KREC + H + n], g_Arec_l[b * KREC + H + n]);
        if (idx < B) g_cnt[idx] = 0;
    }
}

// ============================================================
// LSTM cell: reduce gate partials + Xg, update h/c
// ============================================================
__global__ void lstm_step(int t)
{
    int idx = blockIdx.x * blockDim.x + threadIdx.x;   // B*H
    int b = idx >> 10, n = idx & 1023;
    size_t row = ((size_t)b * T + t) * G4;
    float gi = g_Xg[row + n];
    float gf = g_Xg[row + H + n];
    float gg = g_Xg[row + 2 * H + n];
    float go = g_Xg[row + 3 * H + n];
#pragma unroll
    for (int p = 0; p < SK_GATES; p++) {
        const float* gp = g_gates_part + (size_t)p * B * G4 + (size_t)b * G4;
        gi += gp[n]; gf += gp[H + n]; gg += gp[2 * H + n]; go += gp[3 * H + n];
    }
    float i_ = 1.f / (1.f + expf(-gi));
    float f_ = 1.f / (1.f + expf(-gf));
    float g_ = tanhf(gg);
    float o_ = 1.f / (1.f + expf(-go));
    float c_new = f_ * g_c[idx] + i_ * g_;
    float h_new = o_ * tanhf(c_new);
    g_c[idx] = c_new;
    g_h[idx] = h_new;
    __nv_bfloat16 hH, hL;
    split2(h_new, hH, hL);
    g_h_h[idx] = hH; g_h_l[idx] = hL;
    g_Arec_h[b * KREC + H + n] = hH; g_Arec_l[b * KREC + H + n] = hL;
    g_Aout_h[b * KREC + H + n] = hH; g_Aout_l[b * KREC + H + n] = hL;
}

// ============================================================
// Flash attention split + fused last-block combine/attn/p_gen.
// ============================================================
__global__ __launch_bounds__(256)
void flash_step(int t, const float* __restrict__ enc,
                const float* __restrict__ input_, const float* __restrict__ W_pt,
                const float* __restrict__ b_pt, float* __restrict__ out)
{
    int b = blockIdx.x, sp = blockIdx.y;
    __shared__ float htil[H];
    __shared__ float accS[8][1024];
    __shared__ float wm[8], wl[8], wf[8];
    __shared__ float fP[NSPLIT];
    __shared__ float sM, sL;
    __shared__ int   sLast;
    int tid = threadIdx.x;

    for (int j = tid; j < H; j += 256) {
        float s = 0.f;
#pragma unroll
        for (int p = 0; p < SK_HTIL; p++) s += g_htil_part[(size_t)p * B * H + b * H + j];
        htil[j] = s;
    }
    __syncthreads();

    int warp = tid >> 5, lane = tid & 31;
    float m = -1e30f, l = 0.f;
    float4 acc[8];
#pragma unroll
    for (int i = 0; i < 8; i++) acc[i] = make_float4(0.f, 0.f, 0.f, 0.f);

    float4 ht[8];
#pragma unroll
    for (int i = 0; i < 8; i++) ht[i] = *(const float4*)&htil[i * 128 + lane * 4];

    const float* encb = enc + (size_t)b * S * H;
    int s0 = sp * 128 + warp * 16;
    for (int si = 0; si < 16; si++) {
        int s = s0 + si;
        const float4* er = (const float4*)(encb + (size_t)s * H) + lane;
        float4 v[8];
#pragma unroll
        for (int i = 0; i < 8; i++) v[i] = er[i * 32];
        float d = 0.f;
#pragma unroll
        for (int i = 0; i < 8; i++)
            d += v[i].x * ht[i].x + v[i].y * ht[i].y + v[i].z * ht[i].z + v[i].w * ht[i].w;
#pragma unroll
        for (int off = 16; off > 0; off >>= 1) d += __shfl_xor_sync(0xffffffffu, d, off);
        if (lane == 0) g_logits[b * S + s] = d;
        float mn = fmaxf(m, d);
        float sc = __expf(m - mn);
        float w  = __expf(d - mn);
        l = l * sc + w;
#pragma unroll
        for (int i = 0; i < 8; i++) {
            acc[i].x = acc[i].x * sc + w * v[i].x;
            acc[i].y = acc[i].y * sc + w * v[i].y;
            acc[i].z = acc[i].z * sc + w * v[i].z;
            acc[i].w = acc[i].w * sc + w * v[i].w;
        }
        m = mn;
    }
#pragma unroll
    for (int i = 0; i < 8; i++) *(float4*)&accS[warp][i * 128 + lane * 4] = acc[i];
    if (lane == 0) { wm[warp] = m; wl[warp] = l; }
    __syncthreads();
    if (tid == 0) {
        float M = -1e30f;
        for (int w0 = 0; w0 < 8; w0++) M = fmaxf(M, wm[w0]);
        float L = 0.f;
        for (int w0 = 0; w0 < 8; w0++) { float f = __expf(wm[w0] - M); wf[w0] = f; L += wl[w0] * f; }
        g_part_m[b * NSPLIT + sp] = M;
        g_part_l[b * NSPLIT + sp] = L;
    }
    __syncthreads();
    for (int j = tid; j < H; j += 256) {
        float s = 0.f;
#pragma unroll
        for (int w0 = 0; w0 < 8; w0++) s += accS[w0][j] * wf[w0];
        g_part_acc[((size_t)b * NSPLIT + sp) * H + j] = s;
    }

    __threadfence();
    __syncthreads();
    if (tid == 0) {
        int old = atomicAdd(&g_cnt[b], 1);
        sLast = (old == NSPLIT - 1);
        if (sLast) { g_cnt[b] = 0; __threadfence(); }
    }
    __syncthreads();
    if (!sLast) return;

    if (tid == 0) {
        float M = -1e30f;
        for (int p = 0; p < NSPLIT; p++) M = fmaxf(M, g_part_m[b * NSPLIT + p]);
        float L = 0.f;
        for (int p = 0; p < NSPLIT; p++) {
            float f = __expf(g_part_m[b * NSPLIT + p] - M);
            fP[p] = f;
            L += g_part_l[b * NSPLIT + p] * f;
        }
        sM = M; sL = L;
    }
    __syncthreads();
    float invL = 1.f / sL;
    for (int j = tid; j < H; j += 256) {
        float ce = 0.f;
#pragma unroll
        for (int p = 0; p < NSPLIT; p++)
            ce += g_part_acc[((size_t)b * NSPLIT + p) * H + j] * fP[p];
        float v = ce * invL;
        htil[j] = v;
        split2(v, g_Aout_h[b * KREC + j], g_Aout_l[b * KREC + j]);
    }
    float M = sM;
    for (int s = tid; s < S; s += 256)
        out[OFF_ATTN + (size_t)t * B * S + (size_t)b * S + s] =
            __expf(g_logits[b * S + s] - M) * invL;
    __syncthreads();

    const float* xk = input_ + ((size_t)b * T + t) * IN_DIM;
    float s = 0.f;
    for (int k = tid; k < IN_DIM; k += 256) s += W_pt[k] * xk[k];
    for (int k = tid; k < H; k += 256)      s += W_pt[IN_DIM + k] * g_h[b * H + k];
    for (int k = tid; k < H; k += 256)      s += W_pt[IN_DIM + H + k] * htil[k];
    float* red = &accS[0][0];
    red[tid] = s;
    __syncthreads();
    for (int st = 128; st > 0; st >>= 1) {
        if (tid < st) red[tid] += red[tid + st];
        __syncthreads();
    }
    if (tid == 0) {
        float p = 1.f / (1.f + expf(-(red[0] + b_pt[0])));
        out[OFF_P + (size_t)b * T + t] = p;
    }
}

// ha = [c_enc, h] @ W_out.T + b_out; write output_ + Arec (ha cols)
__global__ void haepi_step(int t, float* __restrict__ out, const float* __restrict__ b_out)
{
    int idx = blockIdx.x * blockDim.x + threadIdx.x;   // B*H
    int b = idx >> 10, n = idx & 1023;
    float v = b_out[n];
#pragma unroll
    for (int p = 0; p < SK_WOUT; p++) v += g_wout_part[(size_t)p * B * H + idx];
    g_Arec[b * KREC + n] = v;
    split2(v, g_Arec_h[b * KREC + n], g_Arec_l[b * KREC + n]);
    out[OFF_OUT + ((size_t)b * T + t) * H + n] = v;
}

__global__ void final_kernel(const float* __restrict__ past_attn_in,
                             const float* __restrict__ past_dehy_in,
                             float* __restrict__ out)
{
    int idx = blockIdx.x * blockDim.x + threadIdx.x;
    if (idx < B * H) {
        out[OFF_H + idx] = g_h[idx];
        out[OFF_C + idx] = g_c[idx];
        int b = idx >> 10, n = idx & 1023;
        out[OFF_HA + idx] = g_Arec[b * KREC + n];
        out[OFF_DEHY + idx] = past_dehy_in[idx];
    }
    if (idx < B * S) out[OFF_PATTN + idx] = past_attn_in[idx];
    if (idx == 0) out[OFF_LOSS] = 0.f;
}

// ============================================================
extern "C" void kernel_launch(void* const* d_in, const int* in_sizes, int n_in,
                              void* d_out, int out_size)
{
    int base = (in_sizes[0] == 1) ? 1 : 0;
    const float* input_    = (const float*)d_in[base + 0];
    const float* hidden_h  = (const float*)d_in[base + 1];
    const float* hidden_c  = (const float*)d_in[base + 2];
    const float* h_attn    = (const float*)d_in[base + 3];
    const float* enc       = (const float*)d_in[base + 4];
    const float* past_attn = (const float*)d_in[base + 5];
    const float* past_dehy = (const float*)d_in[base + 7];
    const float* W_ih  = (const float*)d_in[base + 8];
    const float* b_ih  = (const float*)d_in[base + 9];
    const float* W_hh  = (const float*)d_in[base + 10];
    const float* b_hh  = (const float*)d_in[base + 11];
    const float* W_attn= (const float*)d_in[base + 12];
    const float* W_out = (const float*)d_in[base + 13];
    const float* b_out = (const float*)d_in[base + 14];
    const float* W_pt  = (const float*)d_in[base + 15];
    const float* b_pt  = (const float*)d_in[base + 16];
    float* out = (float*)d_out;

    float *pXg, *pbg, *pGates, *pHtil, *pWoutp;
    __nv_bfloat16 *pWrh, *pWrl, *pWath, *pWatl, *pWouth, *pWoutl, *pWihh, *pWihl;
    __nv_bfloat16 *pInh, *pInl, *pArech, *pArecl, *pAouth, *pAoutl, *pHh, *pHl;
    cudaGetSymbolAddress((void**)&pXg,    g_Xg);
    cudaGetSymbolAddress((void**)&pbg,    g_biasg);
    cudaGetSymbolAddress((void**)&pGates, g_gates_part);
    cudaGetSymbolAddress((void**)&pHtil,  g_htil_part);
    cudaGetSymbolAddress((void**)&pWoutp, g_wout_part);
    cudaGetSymbolAddress((void**)&pWrh,   g_Wr_h);
    cudaGetSymbolAddress((void**)&pWrl,   g_Wr_l);
    cudaGetSymbolAddress((void**)&pWath,  g_Wat_h);
    cudaGetSymbolAddress((void**)&pWatl,  g_Wat_l);
    cudaGetSymbolAddress((void**)&pWouth, g_Wout_h);
    cudaGetSymbolAddress((void**)&pWoutl, g_Wout_l);
    cudaGetSymbolAddress((void**)&pWihh,  g_Wih_h);
    cudaGetSymbolAddress((void**)&pWihl,  g_Wih_l);
    cudaGetSymbolAddress((void**)&pInh,   g_in_h);
    cudaGetSymbolAddress((void**)&pInl,   g_in_l);
    cudaGetSymbolAddress((void**)&pArech, g_Arec_h);
    cudaGetSymbolAddress((void**)&pArecl, g_Arec_l);
    cudaGetSymbolAddress((void**)&pAouth, g_Aout_h);
    cudaGetSymbolAddress((void**)&pAoutl, g_Aout_l);
    cudaGetSymbolAddress((void**)&pHh,    g_h_h);
    cudaGetSymbolAddress((void**)&pHl,    g_h_l);

    static bool attr_set = false;
    if (!attr_set) {
        cudaFuncSetAttribute(hgemm_tn, cudaFuncAttributeMaxDynamicSharedMemorySize,
                             SMEM_BYTES);
        attr_set = true;
    }

    prep_kernel<<<2048, 256>>>(W_ih, W_hh, b_ih, b_hh, W_attn, W_out, input_);
    init_kernel<<<(B * H + 255) / 256, 256>>>(hidden_h, hidden_c, h_attn);

    // Xg = input_ @ W_ih[:, :IN].T + (b_ih + b_hh)
    hgemm_tn<<<dim3(G4 / 128, (B * T) / 128, 1), 256, SMEM_BYTES>>>(
        pInh, pInl, IN_DIM, pWihh, pWihl, IN_DIM, pXg, B * T, G4, IN_DIM, pbg);

    for (int t = 0; t < T; t++) {
        // gates partial: [ha, h] @ [W_ih[:,IN:], W_hh].T
        hgemm_tn<<<dim3(G4 / 128, 1, SK_GATES), 256, SMEM_BYTES>>>(
            pArech, pArecl, KREC, pWrh, pWrl, KREC, pGates, B, G4,
            KREC / SK_GATES, nullptr);
        lstm_step<<<(B * H) / 256, 256>>>(t);
        // h~ = h @ W_attn
        hgemm_tn<<<dim3(H / 128, 1, SK_HTIL), 256, SMEM_BYTES>>>(
            pHh, pHl, H, pWath, pWatl, H, pHtil, B, H, H / SK_HTIL, nullptr);
        flash_step<<<dim3(B, NSPLIT), 256>>>(t, enc, input_, W_pt, b_pt, out);
        // ha partial: [c_enc, h] @ W_out.T
        hgemm_tn<<<dim3(H / 128, 1, SK_WOUT), 256, SMEM_BYTES>>>(
            pAouth, pAoutl, KREC, pWouth, pWoutl, KREC, pWoutp, B, H,
            KREC / SK_WOUT, nullptr);
        haepi_step<<<(B * H) / 256, 256>>>(t, out, b_out);
    }
    final_kernel<<<(B * H + 255) / 256, 256>>>(past_attn, past_dehy, out);
}